// round 3
// baseline (speedup 1.0000x reference)
#include <cuda_runtime.h>
#include <cuda_bf16.h>
#include <mma.h>
#include <type_traits>

using namespace nvcuda;

// ---------------- problem constants ----------------
#define DD    4096
#define BATCH 2
#define SEQ   2048
#define NROWS (BATCH*SEQ)   // 4096 tokens total

// ---------------- scratch (static device arrays; no allocation) ----------------
__device__ float g_xA[(size_t)NROWS * DD];          // 64 MB
__device__ float g_xB[(size_t)NROWS * DD];          // 64 MB
__device__ float g_xC[(size_t)NROWS * DD];          // 64 MB
__device__ float g_xSq[(size_t)BATCH * DD * DD];    // 128 MB
__device__ float g_xO[(size_t)NROWS * DD];          // 64 MB

// ---------------- tf32 WMMA GEMM ----------------
// C[m,n] = sum_k A(m,k) * B(k,n)
//   AT=false: A(m,k) = A[m*lda + k]     AT=true: A(m,k) = A[k*lda + m]
//   BT=false: B(k,n) = B[k*ldb + n]     BT=true: B(k,n) = B[n*ldb + k]
// Tiles are stored in smem AS LOADED (no transpose on store); transposed
// operand cases use col_major WMMA fragments instead.
// grid: (N/128, M/128, nbatch), 256 threads (8 warps: 4 along M x 2 along N).

constexpr int BM = 128, BN = 128, BK = 32;

template <bool AT, bool BT>
__global__ __launch_bounds__(256)
void gemm_tf32(const float* __restrict__ A, const float* __restrict__ B,
               float* __restrict__ C,
               int K, int lda, int ldb, int ldc,
               long long bsA, long long bsB, long long bsC)
{
    // smem leading dims (padded)
    constexpr int LDAS = AT ? (BM + 4) : (BK + 4);   // AT: [BK][BM+4], else [BM][BK+4]
    constexpr int LDBS = BT ? (BK + 4) : (BN + 8);   // BT: [BN][BK+4], else [BK][BN+8]
    constexpr int A_ROWS = AT ? BK : BM;
    constexpr int B_ROWS = BT ? BN : BK;

    __shared__ float As[A_ROWS][LDAS];
    __shared__ float Bs[B_ROWS][LDBS];

    const int bz = blockIdx.z;
    A += (size_t)bz * bsA;
    B += (size_t)bz * bsB;
    C += (size_t)bz * bsC;

    const int m0 = blockIdx.y * BM;
    const int n0 = blockIdx.x * BN;
    const int tid  = threadIdx.x;
    const int warp = tid >> 5;
    const int wm = warp & 3;    // 4 warps along M: 32 rows each
    const int wn = warp >> 2;   // 2 warps along N: 64 cols each

    float4 ra[4], rb[4];

    // each tile is 128x32 floats = 1024 float4 = 4 per thread
    auto loadA = [&](int k0) {
        #pragma unroll
        for (int i = 0; i < 4; i++) {
            int lin = tid + i * 256;
            if (!AT) {          // [128 m][8 k4]
                int r = lin >> 3, c4 = lin & 7;
                ra[i] = *(const float4*)(A + (size_t)(m0 + r) * lda + k0 + c4 * 4);
            } else {            // [32 k][32 m4]
                int r = lin >> 5, c4 = lin & 31;
                ra[i] = *(const float4*)(A + (size_t)(k0 + r) * lda + m0 + c4 * 4);
            }
        }
    };
    auto loadB = [&](int k0) {
        #pragma unroll
        for (int i = 0; i < 4; i++) {
            int lin = tid + i * 256;
            if (!BT) {          // [32 k][32 n4]
                int r = lin >> 5, c4 = lin & 31;
                rb[i] = *(const float4*)(B + (size_t)(k0 + r) * ldb + n0 + c4 * 4);
            } else {            // [128 n][8 k4]
                int r = lin >> 3, c4 = lin & 7;
                rb[i] = *(const float4*)(B + (size_t)(n0 + r) * ldb + k0 + c4 * 4);
            }
        }
    };
    auto storeA = [&]() {
        #pragma unroll
        for (int i = 0; i < 4; i++) {
            int lin = tid + i * 256;
            int r = AT ? (lin >> 5) : (lin >> 3);
            int c4 = AT ? (lin & 31) : (lin & 7);
            *(float4*)&As[r][c4 * 4] = ra[i];
        }
    };
    auto storeB = [&]() {
        #pragma unroll
        for (int i = 0; i < 4; i++) {
            int lin = tid + i * 256;
            int r = BT ? (lin >> 3) : (lin >> 5);
            int c4 = BT ? (lin & 7) : (lin & 31);
            *(float4*)&Bs[r][c4 * 4] = rb[i];
        }
    };

    using ALayout = typename std::conditional<AT, wmma::col_major, wmma::row_major>::type;
    using BLayout = typename std::conditional<BT, wmma::col_major, wmma::row_major>::type;

    wmma::fragment<wmma::accumulator, 16, 16, 8, float> cf[2][4];
    #pragma unroll
    for (int mi = 0; mi < 2; mi++)
        #pragma unroll
        for (int ni = 0; ni < 4; ni++)
            wmma::fill_fragment(cf[mi][ni], 0.0f);

    const int ktiles = K / BK;
    loadA(0); loadB(0);
    storeA(); storeB();
    __syncthreads();

    for (int t = 0; t < ktiles; t++) {
        if (t + 1 < ktiles) { loadA((t + 1) * BK); loadB((t + 1) * BK); }

        #pragma unroll
        for (int kk = 0; kk < BK; kk += 8) {
            wmma::fragment<wmma::matrix_a, 16, 16, 8, wmma::precision::tf32, ALayout> af[2];
            wmma::fragment<wmma::matrix_b, 16, 16, 8, wmma::precision::tf32, BLayout> bf[4];
            #pragma unroll
            for (int mi = 0; mi < 2; mi++) {
                // element (m,k): !AT at As[m][k] (row_major, ld=LDAS)
                //                 AT at As[k][m] (col_major, ld=LDAS)
                const float* ap = AT ? &As[kk][wm * 32 + mi * 16]
                                     : &As[wm * 32 + mi * 16][kk];
                wmma::load_matrix_sync(af[mi], ap, LDAS);
                #pragma unroll
                for (int e = 0; e < af[mi].num_elements; e++)
                    af[mi].x[e] = wmma::__float_to_tf32(af[mi].x[e]);
            }
            #pragma unroll
            for (int ni = 0; ni < 4; ni++) {
                // element (k,n): !BT at Bs[k][n] (row_major, ld=LDBS)
                //                 BT at Bs[n][k] (col_major, ld=LDBS)
                const float* bp = BT ? &Bs[wn * 64 + ni * 16][kk]
                                     : &Bs[kk][wn * 64 + ni * 16];
                wmma::load_matrix_sync(bf[ni], bp, LDBS);
                #pragma unroll
                for (int e = 0; e < bf[ni].num_elements; e++)
                    bf[ni].x[e] = wmma::__float_to_tf32(bf[ni].x[e]);
            }
            #pragma unroll
            for (int mi = 0; mi < 2; mi++)
                #pragma unroll
                for (int ni = 0; ni < 4; ni++)
                    wmma::mma_sync(cf[mi][ni], af[mi], bf[ni], cf[mi][ni]);
        }
        __syncthreads();
        if (t + 1 < ktiles) { storeA(); storeB(); __syncthreads(); }
    }

    #pragma unroll
    for (int mi = 0; mi < 2; mi++)
        #pragma unroll
        for (int ni = 0; ni < 4; ni++)
            wmma::store_matrix_sync(
                C + (size_t)(m0 + wm * 32 + mi * 16) * ldc + n0 + wn * 64 + ni * 16,
                cf[mi][ni], ldc, wmma::mem_row_major);
}

// ---------------- row softmax (row length 4096, one 256-thread block per row) ----
__global__ __launch_bounds__(256)
void softmax_rows(float* __restrict__ data)
{
    float* row = data + (size_t)blockIdx.x * DD;
    const int t = threadIdx.x;
    const int lane = t & 31, wid = t >> 5;
    __shared__ float sred[8];

    float4 v[4];
    float mx = -1e30f;
    #pragma unroll
    for (int i = 0; i < 4; i++) {
        v[i] = reinterpret_cast<float4*>(row)[t + i * 256];
        mx = fmaxf(mx, fmaxf(fmaxf(v[i].x, v[i].y), fmaxf(v[i].z, v[i].w)));
    }
    #pragma unroll
    for (int o = 16; o; o >>= 1) mx = fmaxf(mx, __shfl_xor_sync(0xffffffffu, mx, o));
    if (lane == 0) sred[wid] = mx;
    __syncthreads();
    if (t == 0) {
        float m2 = sred[0];
        #pragma unroll
        for (int i = 1; i < 8; i++) m2 = fmaxf(m2, sred[i]);
        sred[0] = m2;
    }
    __syncthreads();
    mx = sred[0];
    __syncthreads();

    float sum = 0.0f;
    #pragma unroll
    for (int i = 0; i < 4; i++) {
        v[i].x = expf(v[i].x - mx);
        v[i].y = expf(v[i].y - mx);
        v[i].z = expf(v[i].z - mx);
        v[i].w = expf(v[i].w - mx);
        sum += (v[i].x + v[i].y) + (v[i].z + v[i].w);
    }
    #pragma unroll
    for (int o = 16; o; o >>= 1) sum += __shfl_xor_sync(0xffffffffu, sum, o);
    if (lane == 0) sred[wid] = sum;
    __syncthreads();
    if (t == 0) {
        float s2 = 0.0f;
        #pragma unroll
        for (int i = 0; i < 8; i++) s2 += sred[i];
        sred[0] = s2;
    }
    __syncthreads();
    const float inv = 1.0f / sred[0];

    #pragma unroll
    for (int i = 0; i < 4; i++) {
        v[i].x *= inv; v[i].y *= inv; v[i].z *= inv; v[i].w *= inv;
        reinterpret_cast<float4*>(row)[t + i * 256] = v[i];
    }
}

// ---------------- silu + residual: out = silu(acc) + x ----------------
__global__ __launch_bounds__(256)
void silu_add(const float* __restrict__ acc, const float* __restrict__ x,
              float* __restrict__ out, int n4)
{
    int i = blockIdx.x * blockDim.x + threadIdx.x;
    if (i >= n4) return;
    float4 a  = reinterpret_cast<const float4*>(acc)[i];
    float4 xv = reinterpret_cast<const float4*>(x)[i];
    a.x = a.x / (1.0f + expf(-a.x)) + xv.x;
    a.y = a.y / (1.0f + expf(-a.y)) + xv.y;
    a.z = a.z / (1.0f + expf(-a.z)) + xv.z;
    a.w = a.w / (1.0f + expf(-a.w)) + xv.w;
    reinterpret_cast<float4*>(out)[i] = a;
}

// ---------------- launch ----------------
extern "C" void kernel_launch(void* const* d_in, const int* in_sizes, int n_in,
                              void* d_out, int out_size)
{
    const float* x  = (const float*)d_in[0];
    const float* W1 = (const float*)d_in[1];
    const float* W2 = (const float*)d_in[2];
    const float* W3 = (const float*)d_in[3];
    const float* W4 = (const float*)d_in[4];
    const float* W5 = (const float*)d_in[5];
    float* out = (float*)d_out;

    float *xA, *xB, *xC, *xSq, *xO;
    cudaGetSymbolAddress((void**)&xA,  g_xA);
    cudaGetSymbolAddress((void**)&xB,  g_xB);
    cudaGetSymbolAddress((void**)&xC,  g_xC);
    cudaGetSymbolAddress((void**)&xSq, g_xSq);
    cudaGetSymbolAddress((void**)&xO,  g_xO);

    const dim3 blk(256);
    const long long sSD  = (long long)SEQ * DD;   // per-batch token-matrix stride
    const long long sDDb = (long long)DD * DD;    // per-batch Gram stride

    // 1-3: xA = x W1^T, xB = x W2^T, xC = x W3^T   (M=NROWS, N=DD, K=DD)
    {
        dim3 grid(DD / BN, NROWS / BM, 1);
        gemm_tf32<false, true><<<grid, blk>>>(x, W1, xA, DD, DD, DD, DD, 0, 0, 0);
        gemm_tf32<false, true><<<grid, blk>>>(x, W2, xB, DD, DD, DD, DD, 0, 0, 0);
        gemm_tf32<false, true><<<grid, blk>>>(x, W3, xC, DD, DD, DD, DD, 0, 0, 0);
    }
    // 4: Gram per batch: xSq[b] = xA[b]^T xB[b]   (M=N=DD, K=SEQ)
    {
        dim3 grid(DD / BN, DD / BM, BATCH);
        gemm_tf32<true, false><<<grid, blk>>>(xA, xB, xSq, SEQ, DD, DD, DD,
                                              sSD, sSD, sDDb);
    }
    // 5: softmax over last axis of xSq  (2*4096 rows)
    softmax_rows<<<BATCH * DD, blk>>>(xSq);
    // 6: xO[b] = xC[b] * P[b]   (M=SEQ, N=DD, K=DD)
    {
        dim3 grid(DD / BN, SEQ / BM, BATCH);
        gemm_tf32<false, false><<<grid, blk>>>(xC, xSq, xO, DD, DD, DD, DD,
                                               sSD, sDDb, sSD);
    }
    // 7: softmax over last axis of xO  (4096 rows)
    softmax_rows<<<NROWS, blk>>>(xO);
    // 8: g_xA (reuse) = xO_sm * W4^T
    {
        dim3 grid(DD / BN, NROWS / BM, 1);
        gemm_tf32<false, true><<<grid, blk>>>(xO, W4, xA, DD, DD, DD, DD, 0, 0, 0);
    }
    // 9: g_xB (reuse) = silu(g_xA) + x
    {
        int n4 = NROWS * DD / 4;
        silu_add<<<(n4 + 255) / 256, blk>>>(xA, x, xB, n4);
    }
    // 10: out = g_xB * W5^T
    {
        dim3 grid(DD / BN, NROWS / BM, 1);
        gemm_tf32<false, true><<<grid, blk>>>(xB, W5, out, DD, DD, DD, DD, 0, 0, 0);
    }
}

// round 8
// speedup vs baseline: 1.3249x; 1.3249x over previous
#include <cuda_runtime.h>
#include <mma.h>
#include <cstdint>
#include <type_traits>
#include <math.h>

using namespace nvcuda;

// ---------------- problem constants ----------------
#define DD    4096
#define BATCH 2
#define SEQ   2048
#define NROWS (BATCH*SEQ)

// ---------------- scratch (static device arrays; no allocation) ----------------
__device__ float g_rx [(size_t)NROWS*DD];    // tf32-rounded x
__device__ float g_rW1[(size_t)DD*DD];
__device__ float g_rW2[(size_t)DD*DD];
__device__ float g_rW3[(size_t)DD*DD];
__device__ float g_rW4[(size_t)DD*DD];
__device__ float g_rW5[(size_t)DD*DD];
__device__ float g_xA [(size_t)NROWS*DD];
__device__ float g_xB [(size_t)NROWS*DD];
__device__ float g_xC [(size_t)NROWS*DD];
__device__ float g_xO [(size_t)NROWS*DD];
__device__ float g_xSq[(size_t)BATCH*DD*DD];

// ---------------- helpers ----------------
__device__ __forceinline__ uint32_t smem_u32(const void* p) {
    uint32_t a;
    asm("{ .reg .u64 t; cvta.to.shared.u64 t, %1; cvt.u32.u64 %0, t; }" : "=r"(a) : "l"(p));
    return a;
}
__device__ __forceinline__ float rna_tf32(float f) {
    uint32_t r;
    asm("cvt.rna.tf32.f32 %0, %1;" : "=r"(r) : "f"(f));
    return __uint_as_float(r);
}
__device__ __forceinline__ void cp16(uint32_t s, const void* g) {
    asm volatile("cp.async.cg.shared.global [%0], [%1], 16;" :: "r"(s), "l"(g));
}
__device__ __forceinline__ void cp_commit() {
    asm volatile("cp.async.commit_group;" ::: "memory");
}
template <int N>
__device__ __forceinline__ void cp_wait() {
    asm volatile("cp.async.wait_group %0;" :: "n"(N) : "memory");
}

// ---------------- tf32 WMMA GEMM with cp.async pipeline ----------------
// C[m,n] = sum_k A(m,k)*B(k,n)
//   AT=false: A(m,k)=A[m*lda+k]   AT=true: A(m,k)=A[k*lda+m]
//   BT=false: B(k,n)=B[k*ldb+n]   BT=true: B(k,n)=B[n*ldb+k]
// EPI: 0 = raw store, 1 = rna-rounded store, 2 = rna(silu(acc)+Aux) store
// grid (N/128, M/128, batch), 256 threads (warps: 4 along M x 2 along N).
// All inputs are assumed already tf32-rounded, so fragments are used
// without per-element cvt (kills the R3 fma/alu overhead + register bloat).

constexpr int BM = 128, BN = 128, BK = 32;
constexpr int SMEM_BYTES = 73728;   // 2 stages x (A + B), worst template case

template <bool AT, bool BT, int EPI>
__global__ __launch_bounds__(256, 2)
void gemm_cp(const float* __restrict__ A, const float* __restrict__ B,
             float* __restrict__ C, const float* __restrict__ Aux,
             int K, int lda, int ldb, int ldc,
             long long bsA, long long bsB, long long bsC)
{
    extern __shared__ float sm[];

    constexpr int LDAS  = AT ? (BM + 8) : (BK + 4);   // 136 or 36 floats
    constexpr int LDBS  = BT ? (BK + 4) : (BN + 8);   // 36 or 136 floats
    constexpr int AROWS = AT ? BK : BM;
    constexpr int BROWS = BT ? BN : BK;
    constexpr int ASZ = AROWS * LDAS;                 // floats per A stage
    constexpr int BSZ = BROWS * LDBS;

    const int bz = blockIdx.z;
    A += (size_t)bz * bsA;
    B += (size_t)bz * bsB;
    C += (size_t)bz * bsC;

    const int m0 = blockIdx.y * BM;
    const int n0 = blockIdx.x * BN;
    const int tid  = threadIdx.x;
    const int warp = tid >> 5;
    const int wm = warp & 3;     // 4 warps x 32 rows
    const int wn = warp >> 2;    // 2 warps x 64 cols

    const uint32_t sbase = smem_u32(sm);

    // ---- async fill of stage s with k-tile t ----
    auto fill = [&](int t, int s) {
        const int k0 = t * BK;
        const uint32_t ab = sbase + (uint32_t)(s * (ASZ + BSZ)) * 4u;
        const uint32_t bb = ab + (uint32_t)ASZ * 4u;
        #pragma unroll
        for (int i = 0; i < 4; i++) {
            int lin = tid + i * 256;
            if (!AT) {              // [128 m][8 k4]
                int r = lin >> 3, c = lin & 7;
                cp16(ab + (uint32_t)(r * LDAS + c * 4) * 4u,
                     A + (size_t)(m0 + r) * lda + k0 + c * 4);
            } else {                // [32 k][32 m4]
                int r = lin >> 5, c = lin & 31;
                cp16(ab + (uint32_t)(r * LDAS + c * 4) * 4u,
                     A + (size_t)(k0 + r) * lda + m0 + c * 4);
            }
        }
        #pragma unroll
        for (int i = 0; i < 4; i++) {
            int lin = tid + i * 256;
            if (BT) {               // [128 n][8 k4]
                int r = lin >> 3, c = lin & 7;
                cp16(bb + (uint32_t)(r * LDBS + c * 4) * 4u,
                     B + (size_t)(n0 + r) * ldb + k0 + c * 4);
            } else {                // [32 k][32 n4]
                int r = lin >> 5, c = lin & 31;
                cp16(bb + (uint32_t)(r * LDBS + c * 4) * 4u,
                     B + (size_t)(k0 + r) * ldb + n0 + c * 4);
            }
        }
    };

    using ALay = typename std::conditional<AT, wmma::col_major, wmma::row_major>::type;
    using BLay = typename std::conditional<BT, wmma::col_major, wmma::row_major>::type;

    wmma::fragment<wmma::accumulator, 16, 16, 8, float> cf[2][4];
    #pragma unroll
    for (int mi = 0; mi < 2; mi++)
        #pragma unroll
        for (int ni = 0; ni < 4; ni++)
            wmma::fill_fragment(cf[mi][ni], 0.0f);

    const int T = K / BK;
    fill(0, 0); cp_commit();

    for (int t = 0; t < T; t++) {
        const int s = t & 1;
        if (t + 1 < T) { fill(t + 1, s ^ 1); cp_commit(); cp_wait<1>(); }
        else           { cp_wait<0>(); }
        __syncthreads();

        const float* As = sm + s * (ASZ + BSZ);
        const float* Bs = As + ASZ;

        #pragma unroll
        for (int kk = 0; kk < BK; kk += 8) {
            wmma::fragment<wmma::matrix_a, 16, 16, 8, wmma::precision::tf32, ALay> af[2];
            wmma::fragment<wmma::matrix_b, 16, 16, 8, wmma::precision::tf32, BLay> bf[4];
            #pragma unroll
            for (int mi = 0; mi < 2; mi++) {
                const float* ap = AT ? &As[kk * LDAS + wm * 32 + mi * 16]
                                     : &As[(wm * 32 + mi * 16) * LDAS + kk];
                wmma::load_matrix_sync(af[mi], ap, LDAS);
            }
            #pragma unroll
            for (int ni = 0; ni < 4; ni++) {
                const float* bp = BT ? &Bs[(wn * 64 + ni * 16) * LDBS + kk]
                                     : &Bs[kk * LDBS + wn * 64 + ni * 16];
                wmma::load_matrix_sync(bf[ni], bp, LDBS);
            }
            #pragma unroll
            for (int mi = 0; mi < 2; mi++)
                #pragma unroll
                for (int ni = 0; ni < 4; ni++)
                    wmma::mma_sync(cf[mi][ni], af[mi], bf[ni], cf[mi][ni]);
        }
        __syncthreads();
    }

    // ---------------- epilogue ----------------
    if (EPI != 2) {
        #pragma unroll
        for (int mi = 0; mi < 2; mi++)
            #pragma unroll
            for (int ni = 0; ni < 4; ni++) {
                if (EPI == 1) {
                    #pragma unroll
                    for (int e = 0; e < cf[mi][ni].num_elements; e++)
                        cf[mi][ni].x[e] = rna_tf32(cf[mi][ni].x[e]);
                }
                wmma::store_matrix_sync(
                    C + (size_t)(m0 + wm * 32 + mi * 16) * ldc + n0 + wn * 64 + ni * 16,
                    cf[mi][ni], ldc, wmma::mem_row_major);
            }
    } else {
        // silu(acc) + Aux, rna-rounded; frag coords recovered via smem roundtrip
        constexpr int LDE = 136;    // 544B rows: 16B-aligned
        #pragma unroll
        for (int mi = 0; mi < 2; mi++)
            #pragma unroll
            for (int ni = 0; ni < 4; ni++)
                wmma::store_matrix_sync(
                    sm + (size_t)(wm * 32 + mi * 16) * LDE + wn * 64 + ni * 16,
                    cf[mi][ni], LDE, wmma::mem_row_major);
        __syncthreads();
        #pragma unroll
        for (int i = 0; i < 16; i++) {
            int lin = tid + i * 256;          // 4096 float4 = 128 rows x 32 chunks
            int r = lin >> 5, c4 = lin & 31;
            float4 v = *(const float4*)&sm[r * LDE + c4 * 4];
            float4 xv = *(const float4*)(Aux + (size_t)(m0 + r) * ldc + n0 + c4 * 4);
            v.x = rna_tf32(v.x / (1.0f + expf(-v.x)) + xv.x);
            v.y = rna_tf32(v.y / (1.0f + expf(-v.y)) + xv.y);
            v.z = rna_tf32(v.z / (1.0f + expf(-v.z)) + xv.z);
            v.w = rna_tf32(v.w / (1.0f + expf(-v.w)) + xv.w);
            *(float4*)(C + (size_t)(m0 + r) * ldc + n0 + c4 * 4) = v;
        }
    }
}

// ---------------- rna pre-round: out[i] = tf32(in[i]) ----------------
__global__ __launch_bounds__(256)
void rna_copy(const float* __restrict__ in, float* __restrict__ out, int n4)
{
    int i = blockIdx.x * blockDim.x + threadIdx.x;
    if (i >= n4) return;
    float4 v = reinterpret_cast<const float4*>(in)[i];
    v.x = rna_tf32(v.x); v.y = rna_tf32(v.y);
    v.z = rna_tf32(v.z); v.w = rna_tf32(v.w);
    reinterpret_cast<float4*>(out)[i] = v;
}

// ---------------- row softmax (row length 4096); optional rna on store ------
__global__ __launch_bounds__(256)
void softmax_rows(float* __restrict__ data, int rnd)
{
    float* row = data + (size_t)blockIdx.x * DD;
    const int t = threadIdx.x;
    const int lane = t & 31, wid = t >> 5;
    __shared__ float sred[8];

    float4 v[4];
    float mx = -1e30f;
    #pragma unroll
    for (int i = 0; i < 4; i++) {
        v[i] = reinterpret_cast<float4*>(row)[t + i * 256];
        mx = fmaxf(mx, fmaxf(fmaxf(v[i].x, v[i].y), fmaxf(v[i].z, v[i].w)));
    }
    #pragma unroll
    for (int o = 16; o; o >>= 1) mx = fmaxf(mx, __shfl_xor_sync(0xffffffffu, mx, o));
    if (lane == 0) sred[wid] = mx;
    __syncthreads();
    if (t == 0) {
        float m2 = sred[0];
        #pragma unroll
        for (int i = 1; i < 8; i++) m2 = fmaxf(m2, sred[i]);
        sred[0] = m2;
    }
    __syncthreads();
    mx = sred[0];
    __syncthreads();

    float sum = 0.0f;
    #pragma unroll
    for (int i = 0; i < 4; i++) {
        v[i].x = expf(v[i].x - mx); v[i].y = expf(v[i].y - mx);
        v[i].z = expf(v[i].z - mx); v[i].w = expf(v[i].w - mx);
        sum += (v[i].x + v[i].y) + (v[i].z + v[i].w);
    }
    #pragma unroll
    for (int o = 16; o; o >>= 1) sum += __shfl_xor_sync(0xffffffffu, sum, o);
    if (lane == 0) sred[wid] = sum;
    __syncthreads();
    if (t == 0) {
        float s2 = 0.0f;
        #pragma unroll
        for (int i = 0; i < 8; i++) s2 += sred[i];
        sred[0] = s2;
    }
    __syncthreads();
    const float inv = 1.0f / sred[0];
    #pragma unroll
    for (int i = 0; i < 4; i++) {
        v[i].x *= inv; v[i].y *= inv; v[i].z *= inv; v[i].w *= inv;
        if (rnd) {
            v[i].x = rna_tf32(v[i].x); v[i].y = rna_tf32(v[i].y);
            v[i].z = rna_tf32(v[i].z); v[i].w = rna_tf32(v[i].w);
        }
        reinterpret_cast<float4*>(row)[t + i * 256] = v[i];
    }
}

// ---------------- launch ----------------
extern "C" void kernel_launch(void* const* d_in, const int* in_sizes, int n_in,
                              void* d_out, int out_size)
{
    const float* x  = (const float*)d_in[0];
    const float* W1 = (const float*)d_in[1];
    const float* W2 = (const float*)d_in[2];
    const float* W3 = (const float*)d_in[3];
    const float* W4 = (const float*)d_in[4];
    const float* W5 = (const float*)d_in[5];
    float* out = (float*)d_out;

    float *rx, *rW1, *rW2, *rW3, *rW4, *rW5, *xA, *xB, *xC, *xO, *xSq;
    cudaGetSymbolAddress((void**)&rx,  g_rx);
    cudaGetSymbolAddress((void**)&rW1, g_rW1);
    cudaGetSymbolAddress((void**)&rW2, g_rW2);
    cudaGetSymbolAddress((void**)&rW3, g_rW3);
    cudaGetSymbolAddress((void**)&rW4, g_rW4);
    cudaGetSymbolAddress((void**)&rW5, g_rW5);
    cudaGetSymbolAddress((void**)&xA,  g_xA);
    cudaGetSymbolAddress((void**)&xB,  g_xB);
    cudaGetSymbolAddress((void**)&xC,  g_xC);
    cudaGetSymbolAddress((void**)&xO,  g_xO);
    cudaGetSymbolAddress((void**)&xSq, g_xSq);

    cudaFuncSetAttribute(gemm_cp<false, true, 1>, cudaFuncAttributeMaxDynamicSharedMemorySize, SMEM_BYTES);
    cudaFuncSetAttribute(gemm_cp<true, false, 0>, cudaFuncAttributeMaxDynamicSharedMemorySize, SMEM_BYTES);
    cudaFuncSetAttribute(gemm_cp<false, false, 0>, cudaFuncAttributeMaxDynamicSharedMemorySize, SMEM_BYTES);
    cudaFuncSetAttribute(gemm_cp<false, true, 2>, cudaFuncAttributeMaxDynamicSharedMemorySize, SMEM_BYTES);
    cudaFuncSetAttribute(gemm_cp<false, true, 0>, cudaFuncAttributeMaxDynamicSharedMemorySize, SMEM_BYTES);

    const dim3 blk(256);
    const long long sSD  = (long long)SEQ * DD;
    const long long sDDb = (long long)DD * DD;
    const int nW4 = DD * DD / 4, nX4 = NROWS * DD / 4;

    // 0: pre-round GEMM inputs to tf32 (rna)
    rna_copy<<<(nX4 + 255) / 256, blk>>>(x,  rx,  nX4);
    rna_copy<<<(nW4 + 255) / 256, blk>>>(W1, rW1, nW4);
    rna_copy<<<(nW4 + 255) / 256, blk>>>(W2, rW2, nW4);
    rna_copy<<<(nW4 + 255) / 256, blk>>>(W3, rW3, nW4);
    rna_copy<<<(nW4 + 255) / 256, blk>>>(W4, rW4, nW4);
    rna_copy<<<(nW4 + 255) / 256, blk>>>(W5, rW5, nW4);

    // 1-3: projections  xA/xB/xC = x * Wi^T   (M=4096, N=4096, K=4096), epi-rounded
    {
        dim3 grid(DD / BN, NROWS / BM, 1);
        gemm_cp<false, true, 1><<<grid, blk, SMEM_BYTES>>>(rx, rW1, xA, nullptr, DD, DD, DD, DD, 0, 0, 0);
        gemm_cp<false, true, 1><<<grid, blk, SMEM_BYTES>>>(rx, rW2, xB, nullptr, DD, DD, DD, DD, 0, 0, 0);
        gemm_cp<false, true, 1><<<grid, blk, SMEM_BYTES>>>(rx, rW3, xC, nullptr, DD, DD, DD, DD, 0, 0, 0);
    }
    // 4: Gram[b][d][e] = sum_s xA[b][s][d] * xB[b][s][e]   (AT, M=N=4096, K=2048)
    {
        dim3 grid(DD / BN, DD / BM, BATCH);
        gemm_cp<true, false, 0><<<grid, blk, SMEM_BYTES>>>(xA, xB, xSq, nullptr, SEQ, DD, DD, DD,
                                                           sSD, sSD, sDDb);
    }
    // 5: softmax rows of xSq (rounded stores -> P is tf32-clean)
    softmax_rows<<<BATCH * DD, blk>>>(xSq, 1);
    // 6: xO[b] = xC[b] * P[b]   (M=2048, N=4096, K=4096)
    {
        dim3 grid(DD / BN, SEQ / BM, BATCH);
        gemm_cp<false, false, 0><<<grid, blk, SMEM_BYTES>>>(xC, xSq, xO, nullptr, DD, DD, DD, DD,
                                                            sSD, sDDb, sSD);
    }
    // 7: softmax rows of xO (rounded)
    softmax_rows<<<NROWS, blk>>>(xO, 1);
    // 8: fused  xB := rna(silu(xO * W4^T) + x)
    {
        dim3 grid(DD / BN, NROWS / BM, 1);
        gemm_cp<false, true, 2><<<grid, blk, SMEM_BYTES>>>(xO, rW4, xB, x, DD, DD, DD, DD, 0, 0, 0);
    }
    // 9: out = xB * W5^T  (raw fp32 store)
    {
        dim3 grid(DD / BN, NROWS / BM, 1);
        gemm_cp<false, true, 0><<<grid, blk, SMEM_BYTES>>>(xB, rW5, out, nullptr, DD, DD, DD, DD, 0, 0, 0);
    }
}

// round 9
// speedup vs baseline: 5.9475x; 4.4890x over previous
#include <cuda_runtime.h>
#include <cuda_fp16.h>
#include <mma.h>
#include <cstdint>
#include <type_traits>
#include <math.h>

using namespace nvcuda;

// ---------------- problem constants ----------------
#define DD    4096
#define BATCH 2
#define SEQ   2048
#define NROWS (BATCH*SEQ)

// ---------------- scratch (static device arrays; no allocation) ----------------
__device__ __half g_hx [(size_t)NROWS*DD];
__device__ __half g_hW1[(size_t)DD*DD];
__device__ __half g_hW2[(size_t)DD*DD];
__device__ __half g_hW3[(size_t)DD*DD];
__device__ __half g_hW4[(size_t)DD*DD];
__device__ __half g_hW5[(size_t)DD*DD];
__device__ __half g_hA [(size_t)NROWS*DD];
__device__ __half g_hB [(size_t)NROWS*DD];
__device__ __half g_hC [(size_t)NROWS*DD];
__device__ __half g_hP [(size_t)BATCH*DD*DD];   // softmax(Gram) probabilities
__device__ __half g_hxO[(size_t)NROWS*DD];      // softmax(xO) probabilities
__device__ __half g_hy [(size_t)NROWS*DD];      // fp16(x + silu(...))
__device__ float  g_fSq[(size_t)BATCH*DD*DD];   // Gram logits (fp32!)
__device__ float  g_fxO[(size_t)NROWS*DD];      // xO logits (fp32!)

// ---------------- helpers ----------------
__device__ __forceinline__ uint32_t smem_u32(const void* p) {
    uint32_t a;
    asm("{ .reg .u64 t; cvta.to.shared.u64 t, %1; cvt.u32.u64 %0, t; }" : "=r"(a) : "l"(p));
    return a;
}
__device__ __forceinline__ void cp16(uint32_t s, const void* g) {
    asm volatile("cp.async.cg.shared.global [%0], [%1], 16;" :: "r"(s), "l"(g));
}
__device__ __forceinline__ void cp_commit() {
    asm volatile("cp.async.commit_group;" ::: "memory");
}
template <int N>
__device__ __forceinline__ void cp_wait() {
    asm volatile("cp.async.wait_group %0;" :: "n"(N) : "memory");
}
// pack 4 floats -> 4 halves (rn) as an 8-byte value
__device__ __forceinline__ uint2 pack_h4(float a, float b, float c, float d) {
    __half2 p0 = __floats2half2_rn(a, b);
    __half2 p1 = __floats2half2_rn(c, d);
    uint2 u;
    u.x = *reinterpret_cast<uint32_t*>(&p0);
    u.y = *reinterpret_cast<uint32_t*>(&p1);
    return u;
}

// ---------------- fp16 WMMA GEMM with cp.async double buffering ----------------
// C[m,n] = sum_k A(m,k)*B(k,n), A/B fp16, accum fp32.
//   AT/BT as before (transposed operand handled by col_major fragments).
// EPI: 0 = fp32 raw store to Cf
//      1 = fp16 store to Ch (smem roundtrip)
//      2 = fp16( silu(acc) + Aux(fp32) ) store to Ch
// grid (N/128, M/128, batch), 256 threads (4 warps along M x 2 along N).

constexpr int BM = 128, BN = 128, BK = 64;
constexpr int SMEM_BYTES = 73728;   // max(2 stages x tiles, 128x136 fp32 roundtrip)

template <bool AT, bool BT, int EPI>
__global__ __launch_bounds__(256, 2)
void hgemm(const __half* __restrict__ A, const __half* __restrict__ B,
           float* __restrict__ Cf, __half* __restrict__ Ch,
           const float* __restrict__ Aux,
           int K, int lda, int ldb, int ldc,
           long long bsA, long long bsB, long long bsC)
{
    extern __shared__ float smf[];
    __half* hsm = reinterpret_cast<__half*>(smf);

    constexpr int LDAS  = AT ? (BM + 8) : (BK + 8);   // halves: 136 or 72
    constexpr int LDBS  = BT ? (BK + 8) : (BN + 8);   // halves: 72 or 136
    constexpr int AROWS = AT ? BK : BM;
    constexpr int BROWS = BT ? BM : BK;
    constexpr int ASZ = AROWS * LDAS;                 // halves per A stage
    constexpr int BSZ = BROWS * LDBS;

    const int bz = blockIdx.z;
    A += (size_t)bz * bsA;
    B += (size_t)bz * bsB;
    Cf = Cf ? Cf + (size_t)bz * bsC : Cf;
    Ch = Ch ? Ch + (size_t)bz * bsC : Ch;

    const int m0 = blockIdx.y * BM;
    const int n0 = blockIdx.x * BN;
    const int tid  = threadIdx.x;
    const int warp = tid >> 5;
    const int wm = warp & 3;     // 4 warps x 32 rows
    const int wn = warp >> 2;    // 2 warps x 64 cols

    const uint32_t sbase = smem_u32(hsm);

    // ---- async fill of stage s with k-tile t (16B = 8 halves per cp) ----
    auto fill = [&](int t, int s) {
        const int k0 = t * BK;
        const uint32_t ab = sbase + (uint32_t)(s * (ASZ + BSZ)) * 2u;
        const uint32_t bb = ab + (uint32_t)ASZ * 2u;
        #pragma unroll
        for (int i = 0; i < 4; i++) {           // A tile: 1024 chunks
            int lin = tid + i * 256;
            if (!AT) {          // [128 m][8 chunks of 8 halves]
                int r = lin >> 3, c = lin & 7;
                cp16(ab + (uint32_t)(r * LDAS + c * 8) * 2u,
                     A + (size_t)(m0 + r) * lda + k0 + c * 8);
            } else {            // [64 k][16 chunks]
                int r = lin >> 4, c = lin & 15;
                cp16(ab + (uint32_t)(r * LDAS + c * 8) * 2u,
                     A + (size_t)(k0 + r) * lda + m0 + c * 8);
            }
        }
        #pragma unroll
        for (int i = 0; i < 4; i++) {           // B tile: 1024 chunks
            int lin = tid + i * 256;
            if (BT) {           // [128 n][8 chunks]
                int r = lin >> 3, c = lin & 7;
                cp16(bb + (uint32_t)(r * LDBS + c * 8) * 2u,
                     B + (size_t)(n0 + r) * ldb + k0 + c * 8);
            } else {            // [64 k][16 chunks]
                int r = lin >> 4, c = lin & 15;
                cp16(bb + (uint32_t)(r * LDBS + c * 8) * 2u,
                     B + (size_t)(k0 + r) * ldb + n0 + c * 8);
            }
        }
    };

    using ALay = typename std::conditional<AT, wmma::col_major, wmma::row_major>::type;
    using BLay = typename std::conditional<BT, wmma::col_major, wmma::row_major>::type;

    wmma::fragment<wmma::accumulator, 16, 16, 16, float> cf[2][4];
    #pragma unroll
    for (int mi = 0; mi < 2; mi++)
        #pragma unroll
        for (int ni = 0; ni < 4; ni++)
            wmma::fill_fragment(cf[mi][ni], 0.0f);

    const int T = K / BK;
    fill(0, 0); cp_commit();

    for (int t = 0; t < T; t++) {
        const int s = t & 1;
        if (t + 1 < T) { fill(t + 1, s ^ 1); cp_commit(); cp_wait<1>(); }
        else           { cp_wait<0>(); }
        __syncthreads();

        const __half* As = hsm + s * (ASZ + BSZ);
        const __half* Bs = As + ASZ;

        #pragma unroll
        for (int kk = 0; kk < BK; kk += 16) {
            wmma::fragment<wmma::matrix_a, 16, 16, 16, __half, ALay> af[2];
            wmma::fragment<wmma::matrix_b, 16, 16, 16, __half, BLay> bf[4];
            #pragma unroll
            for (int mi = 0; mi < 2; mi++) {
                const __half* ap = AT ? &As[kk * LDAS + wm * 32 + mi * 16]
                                      : &As[(wm * 32 + mi * 16) * LDAS + kk];
                wmma::load_matrix_sync(af[mi], ap, LDAS);
            }
            #pragma unroll
            for (int ni = 0; ni < 4; ni++) {
                const __half* bp = BT ? &Bs[(wn * 64 + ni * 16) * LDBS + kk]
                                      : &Bs[kk * LDBS + wn * 64 + ni * 16];
                wmma::load_matrix_sync(bf[ni], bp, LDBS);
            }
            #pragma unroll
            for (int mi = 0; mi < 2; mi++)
                #pragma unroll
                for (int ni = 0; ni < 4; ni++)
                    wmma::mma_sync(cf[mi][ni], af[mi], bf[ni], cf[mi][ni]);
        }
        __syncthreads();
    }

    // ---------------- epilogue ----------------
    if (EPI == 0) {
        #pragma unroll
        for (int mi = 0; mi < 2; mi++)
            #pragma unroll
            for (int ni = 0; ni < 4; ni++)
                wmma::store_matrix_sync(
                    Cf + (size_t)(m0 + wm * 32 + mi * 16) * ldc + n0 + wn * 64 + ni * 16,
                    cf[mi][ni], ldc, wmma::mem_row_major);
    } else {
        // fp32 smem roundtrip (frag coords opaque), then fp16 convert (+silu)
        constexpr int LDE = 136;    // floats; 544B rows, 16B-aligned
        #pragma unroll
        for (int mi = 0; mi < 2; mi++)
            #pragma unroll
            for (int ni = 0; ni < 4; ni++)
                wmma::store_matrix_sync(
                    smf + (size_t)(wm * 32 + mi * 16) * LDE + wn * 64 + ni * 16,
                    cf[mi][ni], LDE, wmma::mem_row_major);
        __syncthreads();
        #pragma unroll
        for (int i = 0; i < 16; i++) {
            int lin = tid + i * 256;          // 4096 float4 = 128 rows x 32 chunks
            int r = lin >> 5, c4 = lin & 31;
            float4 v = *(const float4*)&smf[r * LDE + c4 * 4];
            if (EPI == 2) {
                float4 xv = *(const float4*)(Aux + (size_t)(m0 + r) * ldc + n0 + c4 * 4);
                v.x = v.x / (1.0f + expf(-v.x)) + xv.x;
                v.y = v.y / (1.0f + expf(-v.y)) + xv.y;
                v.z = v.z / (1.0f + expf(-v.z)) + xv.z;
                v.w = v.w / (1.0f + expf(-v.w)) + xv.w;
            }
            *(uint2*)(Ch + (size_t)(m0 + r) * ldc + n0 + c4 * 4)
                = pack_h4(v.x, v.y, v.z, v.w);
        }
    }
}

// ---------------- fp32 -> fp16 convert ----------------
__global__ __launch_bounds__(256)
void f2h(const float* __restrict__ in, __half* __restrict__ out, int n4)
{
    int i = blockIdx.x * blockDim.x + threadIdx.x;
    if (i >= n4) return;
    float4 v = reinterpret_cast<const float4*>(in)[i];
    reinterpret_cast<uint2*>(out)[i] = pack_h4(v.x, v.y, v.z, v.w);
}

// 5 weight matrices in one launch (keeps launch count low so ncu hits a GEMM)
__global__ __launch_bounds__(256)
void f2h_w5(const float* s0, const float* s1, const float* s2,
            const float* s3, const float* s4,
            __half* d0, __half* d1, __half* d2, __half* d3, __half* d4, int n4)
{
    int i = blockIdx.x * blockDim.x + threadIdx.x;
    if (i >= n4) return;
    const float* s; __half* d;
    switch (blockIdx.z) {
        case 0: s = s0; d = d0; break;
        case 1: s = s1; d = d1; break;
        case 2: s = s2; d = d2; break;
        case 3: s = s3; d = d3; break;
        default: s = s4; d = d4; break;
    }
    float4 v = reinterpret_cast<const float4*>(s)[i];
    reinterpret_cast<uint2*>(d)[i] = pack_h4(v.x, v.y, v.z, v.w);
}

// ---------------- row softmax: fp32 logits in, fp16 probabilities out --------
__global__ __launch_bounds__(256)
void softmax_f2h(const float* __restrict__ in, __half* __restrict__ out)
{
    const float* row = in + (size_t)blockIdx.x * DD;
    __half* orow = out + (size_t)blockIdx.x * DD;
    const int t = threadIdx.x;
    const int lane = t & 31, wid = t >> 5;
    __shared__ float sred[8];

    float4 v[4];
    float mx = -1e30f;
    #pragma unroll
    for (int i = 0; i < 4; i++) {
        v[i] = reinterpret_cast<const float4*>(row)[t + i * 256];
        mx = fmaxf(mx, fmaxf(fmaxf(v[i].x, v[i].y), fmaxf(v[i].z, v[i].w)));
    }
    #pragma unroll
    for (int o = 16; o; o >>= 1) mx = fmaxf(mx, __shfl_xor_sync(0xffffffffu, mx, o));
    if (lane == 0) sred[wid] = mx;
    __syncthreads();
    if (t == 0) {
        float m2 = sred[0];
        #pragma unroll
        for (int i = 1; i < 8; i++) m2 = fmaxf(m2, sred[i]);
        sred[0] = m2;
    }
    __syncthreads();
    mx = sred[0];
    __syncthreads();

    float sum = 0.0f;
    #pragma unroll
    for (int i = 0; i < 4; i++) {
        v[i].x = expf(v[i].x - mx); v[i].y = expf(v[i].y - mx);
        v[i].z = expf(v[i].z - mx); v[i].w = expf(v[i].w - mx);
        sum += (v[i].x + v[i].y) + (v[i].z + v[i].w);
    }
    #pragma unroll
    for (int o = 16; o; o >>= 1) sum += __shfl_xor_sync(0xffffffffu, sum, o);
    if (lane == 0) sred[wid] = sum;
    __syncthreads();
    if (t == 0) {
        float s2 = 0.0f;
        #pragma unroll
        for (int i = 0; i < 8; i++) s2 += sred[i];
        sred[0] = s2;
    }
    __syncthreads();
    const float inv = 1.0f / sred[0];

    #pragma unroll
    for (int i = 0; i < 4; i++) {
        reinterpret_cast<uint2*>(orow)[t + i * 256]
            = pack_h4(v[i].x * inv, v[i].y * inv, v[i].z * inv, v[i].w * inv);
    }
}

// ---------------- launch ----------------
extern "C" void kernel_launch(void* const* d_in, const int* in_sizes, int n_in,
                              void* d_out, int out_size)
{
    const float* x  = (const float*)d_in[0];
    const float* W1 = (const float*)d_in[1];
    const float* W2 = (const float*)d_in[2];
    const float* W3 = (const float*)d_in[3];
    const float* W4 = (const float*)d_in[4];
    const float* W5 = (const float*)d_in[5];
    float* out = (float*)d_out;

    __half *hx, *hW1, *hW2, *hW3, *hW4, *hW5, *hA, *hB, *hC, *hP, *hxO, *hy;
    float *fSq, *fxO;
    cudaGetSymbolAddress((void**)&hx,  g_hx);
    cudaGetSymbolAddress((void**)&hW1, g_hW1);
    cudaGetSymbolAddress((void**)&hW2, g_hW2);
    cudaGetSymbolAddress((void**)&hW3, g_hW3);
    cudaGetSymbolAddress((void**)&hW4, g_hW4);
    cudaGetSymbolAddress((void**)&hW5, g_hW5);
    cudaGetSymbolAddress((void**)&hA,  g_hA);
    cudaGetSymbolAddress((void**)&hB,  g_hB);
    cudaGetSymbolAddress((void**)&hC,  g_hC);
    cudaGetSymbolAddress((void**)&hP,  g_hP);
    cudaGetSymbolAddress((void**)&hxO, g_hxO);
    cudaGetSymbolAddress((void**)&hy,  g_hy);
    cudaGetSymbolAddress((void**)&fSq, g_fSq);
    cudaGetSymbolAddress((void**)&fxO, g_fxO);

    cudaFuncSetAttribute(hgemm<false, true, 1>, cudaFuncAttributeMaxDynamicSharedMemorySize, SMEM_BYTES);
    cudaFuncSetAttribute(hgemm<true, false, 0>, cudaFuncAttributeMaxDynamicSharedMemorySize, SMEM_BYTES);
    cudaFuncSetAttribute(hgemm<false, false, 0>, cudaFuncAttributeMaxDynamicSharedMemorySize, SMEM_BYTES);
    cudaFuncSetAttribute(hgemm<false, true, 2>, cudaFuncAttributeMaxDynamicSharedMemorySize, SMEM_BYTES);
    cudaFuncSetAttribute(hgemm<false, true, 0>, cudaFuncAttributeMaxDynamicSharedMemorySize, SMEM_BYTES);

    const dim3 blk(256);
    const long long sSD  = (long long)SEQ * DD;
    const long long sDDb = (long long)DD * DD;
    const int nW4 = DD * DD / 4, nX4 = NROWS * DD / 4;

    // launch 1-2: fp16 conversions
    f2h<<<(nX4 + 255) / 256, blk>>>(x, hx, nX4);
    {
        dim3 g((nW4 + 255) / 256, 1, 5);
        f2h_w5<<<g, blk>>>(W1, W2, W3, W4, W5, hW1, hW2, hW3, hW4, hW5, nW4);
    }
    // launches 3-5: projections -> fp16
    {
        dim3 grid(DD / BN, NROWS / BM, 1);
        hgemm<false, true, 1><<<grid, blk, SMEM_BYTES>>>(hx, hW1, nullptr, hA, nullptr, DD, DD, DD, DD, 0, 0, 0);
        hgemm<false, true, 1><<<grid, blk, SMEM_BYTES>>>(hx, hW2, nullptr, hB, nullptr, DD, DD, DD, DD, 0, 0, 0);
        hgemm<false, true, 1><<<grid, blk, SMEM_BYTES>>>(hx, hW3, nullptr, hC, nullptr, DD, DD, DD, DD, 0, 0, 0);
    }
    // launch 6 (ncu captures this): Gram logits -> fp32
    {
        dim3 grid(DD / BN, DD / BM, BATCH);
        hgemm<true, false, 0><<<grid, blk, SMEM_BYTES>>>(hA, hB, fSq, nullptr, nullptr, SEQ, DD, DD, DD,
                                                         sSD, sSD, sDDb);
    }
    // softmax over Gram rows -> fp16 probabilities
    softmax_f2h<<<BATCH * DD, blk>>>(fSq, hP);
    // xO logits = xC * P -> fp32
    {
        dim3 grid(DD / BN, SEQ / BM, BATCH);
        hgemm<false, false, 0><<<grid, blk, SMEM_BYTES>>>(hC, hP, fxO, nullptr, nullptr, DD, DD, DD, DD,
                                                          sSD, sDDb, sSD);
    }
    // softmax over xO rows -> fp16
    softmax_f2h<<<NROWS, blk>>>(fxO, hxO);
    // fused: hy = fp16( silu(hxO * W4^T) + x )
    {
        dim3 grid(DD / BN, NROWS / BM, 1);
        hgemm<false, true, 2><<<grid, blk, SMEM_BYTES>>>(hxO, hW4, nullptr, hy, x, DD, DD, DD, DD, 0, 0, 0);
    }
    // out = hy * W5^T -> fp32
    {
        dim3 grid(DD / BN, NROWS / BM, 1);
        hgemm<false, true, 0><<<grid, blk, SMEM_BYTES>>>(hy, hW5, out, nullptr, nullptr, DD, DD, DD, DD, 0, 0, 0);
    }
}

// round 14
// speedup vs baseline: 5.9514x; 1.0007x over previous
#include <cuda_runtime.h>
#include <cuda_fp16.h>
#include <mma.h>
#include <cstdint>
#include <type_traits>
#include <math.h>

using namespace nvcuda;

// ---------------- problem constants ----------------
#define DD    4096
#define BATCH 2
#define SEQ   2048
#define NROWS (BATCH*SEQ)

// ---------------- scratch (static device arrays; no allocation) ----------------
__device__ __half g_hx [(size_t)NROWS*DD];
__device__ __half g_hW1[(size_t)DD*DD];
__device__ __half g_hW2[(size_t)DD*DD];
__device__ __half g_hW3[(size_t)DD*DD];
__device__ __half g_hW4[(size_t)DD*DD];
__device__ __half g_hW5[(size_t)DD*DD];
__device__ __half g_hA [(size_t)NROWS*DD];
__device__ __half g_hB [(size_t)NROWS*DD];
__device__ __half g_hC [(size_t)NROWS*DD];
__device__ __half g_hP [(size_t)BATCH*DD*DD];   // softmax(Gram) probabilities
__device__ __half g_hxO[(size_t)NROWS*DD];      // softmax(xO) probabilities
__device__ __half g_hy [(size_t)NROWS*DD];      // fp16(x + silu(...))
__device__ float  g_fSq[(size_t)BATCH*DD*DD];   // Gram logits (fp32!)
__device__ float  g_fxO[(size_t)NROWS*DD];      // xO logits (fp32!)

// ---------------- helpers ----------------
__device__ __forceinline__ uint32_t smem_u32(const void* p) {
    uint32_t a;
    asm("{ .reg .u64 t; cvta.to.shared.u64 t, %1; cvt.u32.u64 %0, t; }" : "=r"(a) : "l"(p));
    return a;
}
__device__ __forceinline__ void cp16(uint32_t s, const void* g) {
    asm volatile("cp.async.cg.shared.global [%0], [%1], 16;" :: "r"(s), "l"(g));
}
__device__ __forceinline__ void cp_commit() {
    asm volatile("cp.async.commit_group;" ::: "memory");
}
template <int N>
__device__ __forceinline__ void cp_wait() {
    asm volatile("cp.async.wait_group %0;" :: "n"(N) : "memory");
}
// pack 4 floats -> 4 halves (rn) as an 8-byte value
__device__ __forceinline__ uint2 pack_h4(float a, float b, float c, float d) {
    __half2 p0 = __floats2half2_rn(a, b);
    __half2 p1 = __floats2half2_rn(c, d);
    uint2 u;
    u.x = *reinterpret_cast<uint32_t*>(&p0);
    u.y = *reinterpret_cast<uint32_t*>(&p1);
    return u;
}

// ---------------- fp16 WMMA GEMM, 3-stage cp.async pipeline ----------------
// C[m,n] = sum_k A(m,k)*B(k,n), A/B fp16, accum fp32.
//   AT/BT: transposed operand handled by col_major fragments.
// EPI: 0 = fp32 raw store to Cf
//      1 = fp16 store to Ch (smem roundtrip)
//      2 = fp16( silu(acc) + Aux(fp32) ) store to Ch
// grid (N/128, M/128, batch), 256 threads (4 warps along M x 2 along N).

constexpr int BM = 128, BN = 128, BK = 64;
constexpr int STAGES = 3;
constexpr int STAGE_HALVES = 18432;            // worst (ASZ+BSZ) across template cases
constexpr int SMEM_BYTES = STAGES * STAGE_HALVES * 2;   // 110592

template <bool AT, bool BT, int EPI>
__global__ __launch_bounds__(256, 2)
void hgemm(const __half* __restrict__ A, const __half* __restrict__ B,
           float* __restrict__ Cf, __half* __restrict__ Ch,
           const float* __restrict__ Aux,
           int K, int lda, int ldb, int ldc,
           long long bsA, long long bsB, long long bsC)
{
    extern __shared__ float smf[];
    __half* hsm = reinterpret_cast<__half*>(smf);

    constexpr int LDAS  = AT ? (BM + 8) : (BK + 8);   // halves: 136 or 72
    constexpr int LDBS  = BT ? (BK + 8) : (BN + 8);   // halves: 72 or 136
    constexpr int AROWS = AT ? BK : BM;
    constexpr int BROWS = BT ? BN : BK;
    constexpr int ASZ = AROWS * LDAS;                 // halves per A stage
    constexpr int BSZ = BROWS * LDBS;
    constexpr int SSZ = ASZ + BSZ;                    // halves per stage

    const int bz = blockIdx.z;
    A += (size_t)bz * bsA;
    B += (size_t)bz * bsB;
    Cf = Cf ? Cf + (size_t)bz * bsC : Cf;
    Ch = Ch ? Ch + (size_t)bz * bsC : Ch;

    const int m0 = blockIdx.y * BM;
    const int n0 = blockIdx.x * BN;
    const int tid  = threadIdx.x;
    const int warp = tid >> 5;
    const int wm = warp & 3;     // 4 warps x 32 rows
    const int wn = warp >> 2;    // 2 warps x 64 cols

    const uint32_t sbase = smem_u32(hsm);

    // ---- async fill of stage slot s with k-tile t (16B = 8 halves per cp) ----
    auto fill = [&](int t, int s) {
        const int k0 = t * BK;
        const uint32_t ab = sbase + (uint32_t)(s * SSZ) * 2u;
        const uint32_t bb = ab + (uint32_t)ASZ * 2u;
        #pragma unroll
        for (int i = 0; i < 4; i++) {           // A tile: 1024 chunks
            int lin = tid + i * 256;
            if (!AT) {          // [128 m][8 chunks of 8 halves]
                int r = lin >> 3, c = lin & 7;
                cp16(ab + (uint32_t)(r * LDAS + c * 8) * 2u,
                     A + (size_t)(m0 + r) * lda + k0 + c * 8);
            } else {            // [64 k][16 chunks]
                int r = lin >> 4, c = lin & 15;
                cp16(ab + (uint32_t)(r * LDAS + c * 8) * 2u,
                     A + (size_t)(k0 + r) * lda + m0 + c * 8);
            }
        }
        #pragma unroll
        for (int i = 0; i < 4; i++) {           // B tile: 1024 chunks
            int lin = tid + i * 256;
            if (BT) {           // [128 n][8 chunks]
                int r = lin >> 3, c = lin & 7;
                cp16(bb + (uint32_t)(r * LDBS + c * 8) * 2u,
                     B + (size_t)(n0 + r) * ldb + k0 + c * 8);
            } else {            // [64 k][16 chunks]
                int r = lin >> 4, c = lin & 15;
                cp16(bb + (uint32_t)(r * LDBS + c * 8) * 2u,
                     B + (size_t)(k0 + r) * ldb + n0 + c * 8);
            }
        }
    };

    using ALay = typename std::conditional<AT, wmma::col_major, wmma::row_major>::type;
    using BLay = typename std::conditional<BT, wmma::col_major, wmma::row_major>::type;

    wmma::fragment<wmma::accumulator, 16, 16, 16, float> cf[2][4];
    #pragma unroll
    for (int mi = 0; mi < 2; mi++)
        #pragma unroll
        for (int ni = 0; ni < 4; ni++)
            wmma::fill_fragment(cf[mi][ni], 0.0f);

    const int T = K / BK;
    // prologue: stages 0 and 1 in flight
    fill(0, 0); cp_commit();
    fill(1, 1); cp_commit();

    int s = 0;                       // stage slot of k-tile t
    int sf = 2;                      // stage slot for k-tile t+2
    for (int t = 0; t < T; t++) {
        cp_wait<1>();                // stage t resident (stage t+1 may be in flight)
        __syncthreads();             // all warps done with compute(t-1) -> slot sf reusable

        // issue next fill immediately (window = 2 compute iterations)
        if (t + 2 < T) fill(t + 2, sf);
        cp_commit();                 // empty group when no fill: keeps accounting exact

        const __half* As = hsm + s * SSZ;
        const __half* Bs = As + ASZ;

        #pragma unroll
        for (int kk = 0; kk < BK; kk += 16) {
            wmma::fragment<wmma::matrix_a, 16, 16, 16, __half, ALay> af[2];
            wmma::fragment<wmma::matrix_b, 16, 16, 16, __half, BLay> bf[4];
            #pragma unroll
            for (int mi = 0; mi < 2; mi++) {
                const __half* ap = AT ? &As[kk * LDAS + wm * 32 + mi * 16]
                                      : &As[(wm * 32 + mi * 16) * LDAS + kk];
                wmma::load_matrix_sync(af[mi], ap, LDAS);
            }
            #pragma unroll
            for (int ni = 0; ni < 4; ni++) {
                const __half* bp = BT ? &Bs[(wn * 64 + ni * 16) * LDBS + kk]
                                      : &Bs[kk * LDBS + wn * 64 + ni * 16];
                wmma::load_matrix_sync(bf[ni], bp, LDBS);
            }
            #pragma unroll
            for (int mi = 0; mi < 2; mi++)
                #pragma unroll
                for (int ni = 0; ni < 4; ni++)
                    wmma::mma_sync(cf[mi][ni], af[mi], bf[ni], cf[mi][ni]);
        }

        s  = (s == STAGES - 1) ? 0 : s + 1;
        sf = (sf == STAGES - 1) ? 0 : sf + 1;
    }
    __syncthreads();   // protect epilogue smem reuse against warps still in compute(T-1)

    // ---------------- epilogue ----------------
    if (EPI == 0) {
        #pragma unroll
        for (int mi = 0; mi < 2; mi++)
            #pragma unroll
            for (int ni = 0; ni < 4; ni++)
                wmma::store_matrix_sync(
                    Cf + (size_t)(m0 + wm * 32 + mi * 16) * ldc + n0 + wn * 64 + ni * 16,
                    cf[mi][ni], ldc, wmma::mem_row_major);
    } else {
        // fp32 smem roundtrip (frag coords opaque), then fp16 convert (+silu)
        constexpr int LDE = 136;    // floats; 544B rows, 16B-aligned
        #pragma unroll
        for (int mi = 0; mi < 2; mi++)
            #pragma unroll
            for (int ni = 0; ni < 4; ni++)
                wmma::store_matrix_sync(
                    smf + (size_t)(wm * 32 + mi * 16) * LDE + wn * 64 + ni * 16,
                    cf[mi][ni], LDE, wmma::mem_row_major);
        __syncthreads();
        #pragma unroll
        for (int i = 0; i < 16; i++) {
            int lin = tid + i * 256;          // 4096 float4 = 128 rows x 32 chunks
            int r = lin >> 5, c4 = lin & 31;
            float4 v = *(const float4*)&smf[r * LDE + c4 * 4];
            if (EPI == 2) {
                float4 xv = *(const float4*)(Aux + (size_t)(m0 + r) * ldc + n0 + c4 * 4);
                v.x = v.x / (1.0f + expf(-v.x)) + xv.x;
                v.y = v.y / (1.0f + expf(-v.y)) + xv.y;
                v.z = v.z / (1.0f + expf(-v.z)) + xv.z;
                v.w = v.w / (1.0f + expf(-v.w)) + xv.w;
            }
            *(uint2*)(Ch + (size_t)(m0 + r) * ldc + n0 + c4 * 4)
                = pack_h4(v.x, v.y, v.z, v.w);
        }
    }
}

// ---------------- fp32 -> fp16 convert ----------------
__global__ __launch_bounds__(256)
void f2h(const float* __restrict__ in, __half* __restrict__ out, int n4)
{
    int i = blockIdx.x * blockDim.x + threadIdx.x;
    if (i >= n4) return;
    float4 v = reinterpret_cast<const float4*>(in)[i];
    reinterpret_cast<uint2*>(out)[i] = pack_h4(v.x, v.y, v.z, v.w);
}

// 5 weight matrices in one launch (keeps launch count low so ncu hits a GEMM)
__global__ __launch_bounds__(256)
void f2h_w5(const float* s0, const float* s1, const float* s2,
            const float* s3, const float* s4,
            __half* d0, __half* d1, __half* d2, __half* d3, __half* d4, int n4)
{
    int i = blockIdx.x * blockDim.x + threadIdx.x;
    if (i >= n4) return;
    const float* s; __half* d;
    switch (blockIdx.z) {
        case 0: s = s0; d = d0; break;
        case 1: s = s1; d = d1; break;
        case 2: s = s2; d = d2; break;
        case 3: s = s3; d = d3; break;
        default: s = s4; d = d4; break;
    }
    float4 v = reinterpret_cast<const float4*>(s)[i];
    reinterpret_cast<uint2*>(d)[i] = pack_h4(v.x, v.y, v.z, v.w);
}

// ---------------- row softmax: fp32 logits in, fp16 probabilities out --------
__global__ __launch_bounds__(256)
void softmax_f2h(const float* __restrict__ in, __half* __restrict__ out)
{
    const float* row = in + (size_t)blockIdx.x * DD;
    __half* orow = out + (size_t)blockIdx.x * DD;
    const int t = threadIdx.x;
    const int lane = t & 31, wid = t >> 5;
    __shared__ float sred[8];

    float4 v[4];
    float mx = -1e30f;
    #pragma unroll
    for (int i = 0; i < 4; i++) {
        v[i] = reinterpret_cast<const float4*>(row)[t + i * 256];
        mx = fmaxf(mx, fmaxf(fmaxf(v[i].x, v[i].y), fmaxf(v[i].z, v[i].w)));
    }
    #pragma unroll
    for (int o = 16; o; o >>= 1) mx = fmaxf(mx, __shfl_xor_sync(0xffffffffu, mx, o));
    if (lane == 0) sred[wid] = mx;
    __syncthreads();
    if (t == 0) {
        float m2 = sred[0];
        #pragma unroll
        for (int i = 1; i < 8; i++) m2 = fmaxf(m2, sred[i]);
        sred[0] = m2;
    }
    __syncthreads();
    mx = sred[0];
    __syncthreads();

    float sum = 0.0f;
    #pragma unroll
    for (int i = 0; i < 4; i++) {
        v[i].x = expf(v[i].x - mx); v[i].y = expf(v[i].y - mx);
        v[i].z = expf(v[i].z - mx); v[i].w = expf(v[i].w - mx);
        sum += (v[i].x + v[i].y) + (v[i].z + v[i].w);
    }
    #pragma unroll
    for (int o = 16; o; o >>= 1) sum += __shfl_xor_sync(0xffffffffu, sum, o);
    if (lane == 0) sred[wid] = sum;
    __syncthreads();
    if (t == 0) {
        float s2 = 0.0f;
        #pragma unroll
        for (int i = 0; i < 8; i++) s2 += sred[i];
        sred[0] = s2;
    }
    __syncthreads();
    const float inv = 1.0f / sred[0];

    #pragma unroll
    for (int i = 0; i < 4; i++) {
        reinterpret_cast<uint2*>(orow)[t + i * 256]
            = pack_h4(v[i].x * inv, v[i].y * inv, v[i].z * inv, v[i].w * inv);
    }
}

// ---------------- launch ----------------
extern "C" void kernel_launch(void* const* d_in, const int* in_sizes, int n_in,
                              void* d_out, int out_size)
{
    const float* x  = (const float*)d_in[0];
    const float* W1 = (const float*)d_in[1];
    const float* W2 = (const float*)d_in[2];
    const float* W3 = (const float*)d_in[3];
    const float* W4 = (const float*)d_in[4];
    const float* W5 = (const float*)d_in[5];
    float* out = (float*)d_out;

    __half *hx, *hW1, *hW2, *hW3, *hW4, *hW5, *hA, *hB, *hC, *hP, *hxO, *hy;
    float *fSq, *fxO;
    cudaGetSymbolAddress((void**)&hx,  g_hx);
    cudaGetSymbolAddress((void**)&hW1, g_hW1);
    cudaGetSymbolAddress((void**)&hW2, g_hW2);
    cudaGetSymbolAddress((void**)&hW3, g_hW3);
    cudaGetSymbolAddress((void**)&hW4, g_hW4);
    cudaGetSymbolAddress((void**)&hW5, g_hW5);
    cudaGetSymbolAddress((void**)&hA,  g_hA);
    cudaGetSymbolAddress((void**)&hB,  g_hB);
    cudaGetSymbolAddress((void**)&hC,  g_hC);
    cudaGetSymbolAddress((void**)&hP,  g_hP);
    cudaGetSymbolAddress((void**)&hxO, g_hxO);
    cudaGetSymbolAddress((void**)&hy,  g_hy);
    cudaGetSymbolAddress((void**)&fSq, g_fSq);
    cudaGetSymbolAddress((void**)&fxO, g_fxO);

    cudaFuncSetAttribute(hgemm<false, true, 1>, cudaFuncAttributeMaxDynamicSharedMemorySize, SMEM_BYTES);
    cudaFuncSetAttribute(hgemm<true, false, 0>, cudaFuncAttributeMaxDynamicSharedMemorySize, SMEM_BYTES);
    cudaFuncSetAttribute(hgemm<false, false, 0>, cudaFuncAttributeMaxDynamicSharedMemorySize, SMEM_BYTES);
    cudaFuncSetAttribute(hgemm<false, true, 2>, cudaFuncAttributeMaxDynamicSharedMemorySize, SMEM_BYTES);
    cudaFuncSetAttribute(hgemm<false, true, 0>, cudaFuncAttributeMaxDynamicSharedMemorySize, SMEM_BYTES);

    const dim3 blk(256);
    const long long sSD  = (long long)SEQ * DD;
    const long long sDDb = (long long)DD * DD;
    const int nW4 = DD * DD / 4, nX4 = NROWS * DD / 4;

    // launch 1-2: fp16 conversions
    f2h<<<(nX4 + 255) / 256, blk>>>(x, hx, nX4);
    {
        dim3 g((nW4 + 255) / 256, 1, 5);
        f2h_w5<<<g, blk>>>(W1, W2, W3, W4, W5, hW1, hW2, hW3, hW4, hW5, nW4);
    }
    // launches 3-5: projections -> fp16
    {
        dim3 grid(DD / BN, NROWS / BM, 1);
        hgemm<false, true, 1><<<grid, blk, SMEM_BYTES>>>(hx, hW1, nullptr, hA, nullptr, DD, DD, DD, DD, 0, 0, 0);
        hgemm<false, true, 1><<<grid, blk, SMEM_BYTES>>>(hx, hW2, nullptr, hB, nullptr, DD, DD, DD, DD, 0, 0, 0);
        hgemm<false, true, 1><<<grid, blk, SMEM_BYTES>>>(hx, hW3, nullptr, hC, nullptr, DD, DD, DD, DD, 0, 0, 0);
    }
    // launch 6 (ncu captures this): Gram logits -> fp32
    {
        dim3 grid(DD / BN, DD / BM, BATCH);
        hgemm<true, false, 0><<<grid, blk, SMEM_BYTES>>>(hA, hB, fSq, nullptr, nullptr, SEQ, DD, DD, DD,
                                                         sSD, sSD, sDDb);
    }
    // softmax over Gram rows -> fp16 probabilities
    softmax_f2h<<<BATCH * DD, blk>>>(fSq, hP);
    // xO logits = xC * P -> fp32
    {
        dim3 grid(DD / BN, SEQ / BM, BATCH);
        hgemm<false, false, 0><<<grid, blk, SMEM_BYTES>>>(hC, hP, fxO, nullptr, nullptr, DD, DD, DD, DD,
                                                          sSD, sDDb, sSD);
    }
    // softmax over xO rows -> fp16
    softmax_f2h<<<NROWS, blk>>>(fxO, hxO);
    // fused: hy = fp16( silu(hxO * W4^T) + x )
    {
        dim3 grid(DD / BN, NROWS / BM, 1);
        hgemm<false, true, 2><<<grid, blk, SMEM_BYTES>>>(hxO, hW4, nullptr, hy, x, DD, DD, DD, DD, 0, 0, 0);
    }
    // out = hy * W5^T -> fp32
    {
        dim3 grid(DD / BN, NROWS / BM, 1);
        hgemm<false, true, 0><<<grid, blk, SMEM_BYTES>>>(hy, hW5, out, nullptr, nullptr, DD, DD, DD, DD, 0, 0, 0);
    }
}